// round 9
// baseline (speedup 1.0000x reference)
#include <cuda_runtime.h>
#include <cstdint>

#define BB    2
#define CC    64
#define NPOS  131072
#define HEADS 4
#define DHEAD 32
#define HID   128
#define TPB   256
#define POSB  128

typedef unsigned long long u64;

// ---------------- device scratch ----------------
__device__ float g_ctx[BB * HEADS * DHEAD * DHEAD];    // raw sum exp(k_d)*v_e
__device__ float g_Z[BB * HEADS * DHEAD];              // sum exp(k_d)
__device__ float g_M[BB * HID * CC];                   // M[b][h*32+d][o]

// ---------------- f32x2 helpers ----------------
__device__ __forceinline__ u64 pack2(float lo, float hi) {
    u64 r; asm("mov.b64 %0, {%1,%2};" : "=l"(r) : "f"(lo), "f"(hi)); return r;
}
__device__ __forceinline__ u64 ffma2(u64 a, u64 b, u64 c) {
    u64 d; asm("fma.rn.f32x2 %0, %1, %2, %3;" : "=l"(d) : "l"(a), "l"(b), "l"(c)); return d;
}
__device__ __forceinline__ u64 fadd2(u64 a, u64 b) {
    u64 d; asm("add.rn.f32x2 %0, %1, %2;" : "=l"(d) : "l"(a), "l"(b)); return d;
}
__device__ __forceinline__ float hsum2(u64 a) {
    float lo, hi; asm("mov.b64 {%0,%1}, %2;" : "=f"(lo), "=f"(hi) : "l"(a)); return lo + hi;
}
__device__ __forceinline__ void unpack2(u64 a, float& lo, float& hi) {
    asm("mov.b64 {%0,%1}, %2;" : "=f"(lo), "=f"(hi) : "l"(a));
}

// ---------------- kernel 0: zero accumulators ----------------
__global__ void la_zero_kernel() {
    int i = blockIdx.x * blockDim.x + threadIdx.x;
    if (i < BB * HEADS * DHEAD * DHEAD) g_ctx[i] = 0.f;
    if (i < BB * HEADS * DHEAD)         g_Z[i]   = 0.f;
}

// ======================= common GEMM building blocks =======================
// W chunk (32 rows x 64 k) staged in smem duplicated: wd[k*34 + row] = (w,w).
// Tile per thread: 4 rows (rg = t>>5, warp-uniform -> W reads broadcast) x
// 4 positions (pg = t&31, ull2 pair loads from xs). Per k: 3 LDS.128 + 8 FFMA2.

__device__ __forceinline__ void wchunk_ldg(float (&wr)[8], const float* __restrict__ wsrc, int t) {
#pragma unroll
    for (int i = 0; i < 8; i++) wr[i] = __ldg(wsrc + t + i * 256);
}
__device__ __forceinline__ void wchunk_sts(u64* wd, const float (&wr)[8], int t) {
#pragma unroll
    for (int i = 0; i < 8; i++) {
        int p = t + i * 256;
        wd[(p & 63) * 34 + (p >> 6)] = pack2(wr[i], wr[i]);
    }
}

__device__ __forceinline__ void gemm32(const u64* __restrict__ wd, const float* __restrict__ xs,
                                       int rg, int pg, u64 (&acc)[4][2]) {
#pragma unroll
    for (int r = 0; r < 4; r++) { acc[r][0] = 0; acc[r][1] = 0; }
#pragma unroll 4
    for (int k = 0; k < 64; k++) {
        ulonglong2 wa = *(const ulonglong2*)(wd + k * 34 + rg * 4);       // rows 0,1 (dup)
        ulonglong2 wb = *(const ulonglong2*)(wd + k * 34 + rg * 4 + 2);   // rows 2,3 (dup)
        ulonglong2 xv = *(const ulonglong2*)(xs + k * 132 + pg * 4);      // 4 pos = 2 pairs
        acc[0][0] = ffma2(wa.x, xv.x, acc[0][0]); acc[0][1] = ffma2(wa.x, xv.y, acc[0][1]);
        acc[1][0] = ffma2(wa.y, xv.x, acc[1][0]); acc[1][1] = ffma2(wa.y, xv.y, acc[1][1]);
        acc[2][0] = ffma2(wb.x, xv.x, acc[2][0]); acc[2][1] = ffma2(wb.x, xv.y, acc[2][1]);
        acc[3][0] = ffma2(wb.y, xv.x, acc[3][0]); acc[3][1] = ffma2(wb.y, xv.y, acc[3][1]);
    }
}

__device__ __forceinline__ void tile_store(float* __restrict__ dst, const u64 (&acc)[4][2],
                                           int rg, int pg, bool do_exp) {
#pragma unroll
    for (int r = 0; r < 4; r++) {
        int row = rg * 4 + r;
#pragma unroll
        for (int pp = 0; pp < 2; pp++) {
            float lo, hi; unpack2(acc[r][pp], lo, hi);
            if (do_exp) { lo = __expf(lo); hi = __expf(hi); }
            *(u64*)(dst + row * 132 + pg * 4 + pp * 2) = pack2(lo, hi);
        }
    }
}

// phase0: per-position channel-LN of x -> xs[ch][132] (positions contiguous).
// 2 threads per position (half = t>>7 handles 32 channels); stats via smem scratch.
__device__ __forceinline__ void phase0_ln(const float* __restrict__ x, int bb, int pos0,
                                          int t, float* xs, float* scratch,
                                          const float* g1s, const float* b1s) {
    const int p = t & 127, half = t >> 7;
    const float* xb = x + (size_t)bb * CC * NPOS + pos0 + p;
    float xr[32];
    float s = 0.f, s2 = 0.f;
#pragma unroll
    for (int c = 0; c < 32; c++) {
        float v = __ldg(xb + (size_t)(half * 32 + c) * NPOS);
        xr[c] = v; s += v; s2 += v * v;
    }
    scratch[half * 128 + p]       = s;
    scratch[256 + half * 128 + p] = s2;
    __syncthreads();
    float st  = scratch[p] + scratch[128 + p];
    float st2 = scratch[256 + p] + scratch[384 + p];
    float mean = st * (1.f / 64.f);
    float rstd = rsqrtf(st2 * (1.f / 64.f) - mean * mean + 1e-5f);
#pragma unroll
    for (int c = 0; c < 32; c++) {
        int ch = half * 32 + c;
        xs[ch * 132 + p] = (xr[c] - mean) * rstd * g1s[ch] + b1s[ch];
    }
}

// ================= pass1: LN1 + K,V GEMMs + ctx/Z partials =================
// smem: wdA/wdB 2x2176 u64 | xs 64x132 | ek 32x132 | vv 32x132 | g1s/b1s 128
#define SM1_FLOATS (2 * 4352 + 64 * 132 + 32 * 132 + 32 * 132 + 128)   // 25728 fl = 102912 B

__global__ __launch_bounds__(TPB, 2)
void la_pass1_kernel(const float* __restrict__ x, const float* __restrict__ g1,
                     const float* __restrict__ b1, const float* __restrict__ wqkv) {
    extern __shared__ float sm1[];
    u64*   wdA = (u64*)sm1;                 // 2176 u64
    u64*   wdB = wdA + 2176;
    float* xs  = sm1 + 2 * 4352;
    float* ek  = xs + 64 * 132;
    float* vv  = ek + 32 * 132;
    float* g1s = vv + 32 * 132;
    float* b1s = g1s + 64;

    const int t    = threadIdx.x;
    const int bb   = blockIdx.y;
    const int pos0 = blockIdx.x * POSB;

    float wr[8];
    wchunk_ldg(wr, wqkv + (size_t)HID * 64, t);     // K head 0
    if (t < 64) { g1s[t] = g1[t]; b1s[t] = b1[t]; }

    phase0_ln(x, bb, pos0, t, xs, ek, g1s, b1s);
    wchunk_sts(wdA, wr, t);
    __syncthreads();

    const int rg = t >> 5, pg = t & 31;
    const int d_own = t >> 3, e0 = t & 7;

    u64 acc[4][2];
    for (int h = 0; h < HEADS; h++) {
        // interval 1: prefetch V_h; GEMM K -> ek (exp); stage V into wdB
        wchunk_ldg(wr, wqkv + (size_t)(2 * HID + h * 32) * 64, t);
        gemm32(wdA, xs, rg, pg, acc);
        tile_store(ek, acc, rg, pg, true);
        wchunk_sts(wdB, wr, t);
        __syncthreads();

        // interval 2: prefetch K_{h+1}; GEMM V -> vv
        if (h < 3) wchunk_ldg(wr, wqkv + (size_t)(HID + (h + 1) * 32) * 64, t);
        gemm32(wdB, xs, rg, pg, acc);
        tile_store(vv, acc, rg, pg, false);
        __syncthreads();

        // interval 3: stage B partial sums; stage next K into wdA
        {
            u64 a0 = 0, a1 = 0, a2 = 0, a3 = 0, za = 0;
            const float* ekr = ek + d_own * 132;
#pragma unroll 4
            for (int tt = 0; tt < POSB; tt += 4) {
                ulonglong2 ap = *(const ulonglong2*)(ekr + tt);
                ulonglong2 b0 = *(const ulonglong2*)(vv + (e0     ) * 132 + tt);
                ulonglong2 b1v= *(const ulonglong2*)(vv + (e0 +  8) * 132 + tt);
                ulonglong2 b2v= *(const ulonglong2*)(vv + (e0 + 16) * 132 + tt);
                ulonglong2 b3v= *(const ulonglong2*)(vv + (e0 + 24) * 132 + tt);
                a0 = ffma2(ap.x, b0.x, a0);  a0 = ffma2(ap.y, b0.y, a0);
                a1 = ffma2(ap.x, b1v.x, a1); a1 = ffma2(ap.y, b1v.y, a1);
                a2 = ffma2(ap.x, b2v.x, a2); a2 = ffma2(ap.y, b2v.y, a2);
                a3 = ffma2(ap.x, b3v.x, a3); a3 = ffma2(ap.y, b3v.y, a3);
                if (e0 == 0) za = fadd2(za, fadd2(ap.x, ap.y));
            }
            float* cb = g_ctx + (size_t)((bb * HEADS + h) * DHEAD + d_own) * DHEAD;
            atomicAdd(cb + e0,      hsum2(a0));
            atomicAdd(cb + e0 +  8, hsum2(a1));
            atomicAdd(cb + e0 + 16, hsum2(a2));
            atomicAdd(cb + e0 + 24, hsum2(a3));
            if (e0 == 0) atomicAdd(g_Z + (bb * HEADS + h) * DHEAD + d_own, hsum2(za));
        }
        if (h < 3) wchunk_sts(wdA, wr, t);
        __syncthreads();
    }
}

// ---------------- kernel 2: fold  M[b][h*32+d][o] = sum_e W_out[o][h*32+e]*ctx[h,d,e]/Z
__global__ void la_fold_kernel(const float* __restrict__ wout) {
    int bb = blockIdx.x;
    for (int idx = threadIdx.x; idx < HID * CC; idx += blockDim.x) {
        int i = idx >> 6, o = idx & 63;
        int h = i >> 5,   d = i & 31;
        const float* cp = g_ctx + (size_t)((bb * HEADS + h) * DHEAD + d) * DHEAD;
        const float* wp = wout + (size_t)o * HID + h * DHEAD;
        float acc = 0.f;
#pragma unroll
        for (int e = 0; e < 32; e++) acc += wp[e] * cp[e];
        g_M[(size_t)bb * HID * CC + i * 64 + o] = acc / g_Z[(bb * HEADS + h) * DHEAD + d];
    }
}

// ======= pass2: LN1 + Q GEMM + softmax + y += M_h q_h + LN2 (q never hits DRAM) =======
// smem: wdA 2176 u64 | mdA/mdB 2x544 ull2 | xs 64x132 | ekq 32x132 | bo/g2s/b2s 192
#define SM2_FLOATS (4352 + 4352 + 64 * 132 + 32 * 132 + 192)   // 21568 fl = 86272 B

__global__ __launch_bounds__(TPB, 2)
void la_pass2_kernel(const float* __restrict__ x, const float* __restrict__ g1,
                     const float* __restrict__ b1, const float* __restrict__ wqkv,
                     const float* __restrict__ bout, const float* __restrict__ g2,
                     const float* __restrict__ b2, float* __restrict__ out) {
    extern __shared__ float sm2[];
    u64*        wdA  = (u64*)sm2;                       // 2176 u64 (Q chunk)
    ulonglong2* mdA  = (ulonglong2*)(sm2 + 4352);       // 32 x 17 ull2 (M rows, o 0..1 of group)
    ulonglong2* mdB  = mdA + 544;                       // 32 x 17 ull2 (o 2..3 of group)
    float* xs  = sm2 + 8704;
    float* ekq = xs + 64 * 132;
    float* bo  = ekq + 32 * 132;
    float* g2s = bo + 64;
    float* b2s = g2s + 64;

    const int t    = threadIdx.x;
    const int bb   = blockIdx.y;
    const int pos0 = blockIdx.x * POSB;

    float wr[8];
    wchunk_ldg(wr, wqkv, t);                            // Q head 0
    if (t < 64) { bo[t] = bout[t]; g2s[t] = g2[t]; b2s[t] = b2[t]; }
    // g1/b1 staged in registers through phase0 via smem region reuse: use ekq tail
    float* g1s = ekq + 512;        // scratch inside ekq (first 512 used for stats)
    float* b1s = g1s + 64;
    if (t < 64) { g1s[t] = g1[t]; b1s[t] = b1[t]; }

    phase0_ln(x, bb, pos0, t, xs, ekq, g1s, b1s);
    wchunk_sts(wdA, wr, t);
    __syncthreads();

    const int rg = t >> 5, pg = t & 31;
    const int og = t & 15, pg2 = t >> 4;     // M-apply tile: 4 o's x 8 positions

    u64 acc_y[4][4];
#pragma unroll
    for (int oi = 0; oi < 4; oi++)
#pragma unroll
        for (int pp = 0; pp < 4; pp++) acc_y[oi][pp] = 0;

    u64 acc[4][2];
    for (int h = 0; h < HEADS; h++) {
        // prefetch this head's M (warps 4-7) while GEMM runs
        float4 mld[4];
        if (t >= 128) {
            int t2 = t - 128;
            int d = t2 >> 2, j = t2 & 3;
            const float* mh = g_M + (size_t)(bb * HEADS + h) * DHEAD * 64 + d * 64;
#pragma unroll
            for (int q = 0; q < 4; q++) mld[q] = *(const float4*)(mh + (j * 4 + q) * 4);
        }
        // interval 1: Q GEMM -> ekq (raw logits)
        gemm32(wdA, xs, rg, pg, acc);
        tile_store(ekq, acc, rg, pg, false);
        __syncthreads();

        // interval 2: warps 0-3 softmax; warps 4-7 build duplicated M tiles
        if (t < 128) {
            float qv[32];
            float mx = -1e30f;
#pragma unroll
            for (int d = 0; d < 32; d++) { qv[d] = ekq[d * 132 + t]; mx = fmaxf(mx, qv[d]); }
            float ss = 0.f;
#pragma unroll
            for (int d = 0; d < 32; d++) { qv[d] = __expf(qv[d] - mx); ss += qv[d]; }
            float qsc = 0.17677669529663687f / ss;
#pragma unroll
            for (int d = 0; d < 32; d++) ekq[d * 132 + t] = qv[d] * qsc;
        } else {
            int t2 = t - 128;
            int d = t2 >> 2, j = t2 & 3;
#pragma unroll
            for (int q = 0; q < 4; q++) {
                int o4 = j * 4 + q;
                mdA[d * 17 + o4] = make_ulonglong2(pack2(mld[q].x, mld[q].x), pack2(mld[q].y, mld[q].y));
                mdB[d * 17 + o4] = make_ulonglong2(pack2(mld[q].z, mld[q].z), pack2(mld[q].w, mld[q].w));
            }
        }
        if (h < 3) wchunk_ldg(wr, wqkv + (size_t)(h + 1) * 32 * 64, t);
        __syncthreads();

        // interval 3: y += M_h @ q_h ; stage next Q chunk
#pragma unroll 2
        for (int d = 0; d < 32; d++) {
            ulonglong2 ma = mdA[d * 17 + og];     // o = og*4, og*4+1 (dup)
            ulonglong2 mb = mdB[d * 17 + og];     // o = og*4+2, og*4+3 (dup)
            ulonglong2 qa = *(const ulonglong2*)(ekq + d * 132 + pg2 * 8);
            ulonglong2 qb = *(const ulonglong2*)(ekq + d * 132 + pg2 * 8 + 4);
            acc_y[0][0] = ffma2(ma.x, qa.x, acc_y[0][0]);
            acc_y[0][1] = ffma2(ma.x, qa.y, acc_y[0][1]);
            acc_y[0][2] = ffma2(ma.x, qb.x, acc_y[0][2]);
            acc_y[0][3] = ffma2(ma.x, qb.y, acc_y[0][3]);
            acc_y[1][0] = ffma2(ma.y, qa.x, acc_y[1][0]);
            acc_y[1][1] = ffma2(ma.y, qa.y, acc_y[1][1]);
            acc_y[1][2] = ffma2(ma.y, qb.x, acc_y[1][2]);
            acc_y[1][3] = ffma2(ma.y, qb.y, acc_y[1][3]);
            acc_y[2][0] = ffma2(mb.x, qa.x, acc_y[2][0]);
            acc_y[2][1] = ffma2(mb.x, qa.y, acc_y[2][1]);
            acc_y[2][2] = ffma2(mb.x, qb.x, acc_y[2][2]);
            acc_y[2][3] = ffma2(mb.x, qb.y, acc_y[2][3]);
            acc_y[3][0] = ffma2(mb.y, qa.x, acc_y[3][0]);
            acc_y[3][1] = ffma2(mb.y, qa.y, acc_y[3][1]);
            acc_y[3][2] = ffma2(mb.y, qb.x, acc_y[3][2]);
            acc_y[3][3] = ffma2(mb.y, qb.y, acc_y[3][3]);
        }
        if (h < 3) wchunk_sts(wdA, wr, t);
        __syncthreads();
    }

    // epilogue: bias, LN2 over 64 channels (shfl across 16 og lanes), store
#pragma unroll
    for (int oi = 0; oi < 4; oi++) {
        int o = og * 4 + oi;
        u64 bp = pack2(bo[o], bo[o]);
#pragma unroll
        for (int pp = 0; pp < 4; pp++) acc_y[oi][pp] = fadd2(acc_y[oi][pp], bp);
    }
    u64 su[4] = {0, 0, 0, 0}, s2u[4] = {0, 0, 0, 0};
#pragma unroll
    for (int oi = 0; oi < 4; oi++)
#pragma unroll
        for (int pp = 0; pp < 4; pp++) {
            su[pp]  = fadd2(su[pp], acc_y[oi][pp]);
            s2u[pp] = ffma2(acc_y[oi][pp], acc_y[oi][pp], s2u[pp]);
        }
#pragma unroll
    for (int m = 1; m < 16; m <<= 1)
#pragma unroll
        for (int pp = 0; pp < 4; pp++) {
            su[pp]  = fadd2(su[pp],  __shfl_xor_sync(0xffffffffu, su[pp],  m));
            s2u[pp] = fadd2(s2u[pp], __shfl_xor_sync(0xffffffffu, s2u[pp], m));
        }
    float mean_[8], rstd_[8];
#pragma unroll
    for (int pp = 0; pp < 4; pp++) {
        float sa, sb, qa, qb; unpack2(su[pp], sa, sb); unpack2(s2u[pp], qa, qb);
        float ma = sa * (1.f / 64.f), mb = sb * (1.f / 64.f);
        mean_[2 * pp] = ma; mean_[2 * pp + 1] = mb;
        rstd_[2 * pp]     = rsqrtf(qa * (1.f / 64.f) - ma * ma + 1e-5f);
        rstd_[2 * pp + 1] = rsqrtf(qb * (1.f / 64.f) - mb * mb + 1e-5f);
    }
    float* ob = out + (size_t)bb * CC * NPOS + pos0 + pg2 * 8;
#pragma unroll
    for (int oi = 0; oi < 4; oi++) {
        int o = og * 4 + oi;
        float ga = g2s[o], bv = b2s[o];
#pragma unroll
        for (int pp = 0; pp < 4; pp++) {
            float ya, yb; unpack2(acc_y[oi][pp], ya, yb);
            float2 v;
            v.x = (ya - mean_[2 * pp])     * rstd_[2 * pp]     * ga + bv;
            v.y = (yb - mean_[2 * pp + 1]) * rstd_[2 * pp + 1] * ga + bv;
            *(float2*)(ob + (size_t)o * NPOS + pp * 2) = v;
        }
    }
}

// ---------------- launch ----------------
extern "C" void kernel_launch(void* const* d_in, const int* in_sizes, int n_in,
                              void* d_out, int out_size) {
    (void)in_sizes; (void)n_in; (void)out_size;
    const float* x    = (const float*)d_in[0];
    const float* g1   = (const float*)d_in[1];
    const float* b1   = (const float*)d_in[2];
    const float* wqkv = (const float*)d_in[3];
    const float* wout = (const float*)d_in[4];
    const float* bout = (const float*)d_in[5];
    const float* g2   = (const float*)d_in[6];
    const float* b2   = (const float*)d_in[7];
    float* y = (float*)d_out;

    cudaFuncSetAttribute(la_pass1_kernel, cudaFuncAttributeMaxDynamicSharedMemorySize,
                         SM1_FLOATS * (int)sizeof(float));
    cudaFuncSetAttribute(la_pass2_kernel, cudaFuncAttributeMaxDynamicSharedMemorySize,
                         SM2_FLOATS * (int)sizeof(float));

    la_zero_kernel<<<33, 256>>>();
    la_pass1_kernel<<<dim3(NPOS / POSB, BB), TPB, SM1_FLOATS * sizeof(float)>>>(x, g1, b1, wqkv);
    la_fold_kernel<<<BB, 256>>>(wout);
    la_pass2_kernel<<<dim3(NPOS / POSB, BB), TPB, SM2_FLOATS * sizeof(float)>>>(
        x, g1, b1, wqkv, bout, g2, b2, y);
}